// round 1
// baseline (speedup 1.0000x reference)
#include <cuda_runtime.h>

// Problem constants (fixed by the reference)
#define BB 8
#define SS 8192
#define DD 768
#define VV 64
#define LL 26
#define NSEG (BB * VV)   // 512
#define NTOK (BB * SS)   // 65536

// Scratch (no allocation allowed in kernel_launch)
__device__ int g_counts[NSEG];
__device__ int g_offsets[NSEG];
__device__ int g_cursor[NSEG];
__device__ int g_index[NTOK];

// ---------------------------------------------------------------------------
// Phase 1a: zero per-segment counters
__global__ void k_zero() {
    int i = blockIdx.x * blockDim.x + threadIdx.x;
    if (i < NSEG) g_counts[i] = 0;
}

// Phase 1b: histogram of (batch, symbol) segments
__global__ void k_hist(const int* __restrict__ ids) {
    int t = blockIdx.x * blockDim.x + threadIdx.x;
    if (t < NTOK) {
        int b = t >> 13;            // t / S
        int v = ids[t];
        atomicAdd(&g_counts[b * VV + v], 1);
    }
}

// Phase 1c: exclusive scan of 512 counters (single block, Hillis-Steele)
__global__ void k_scan() {
    __shared__ int sh[NSEG];
    int tid = threadIdx.x;
    int my = g_counts[tid];
    sh[tid] = my;
    __syncthreads();
    #pragma unroll
    for (int off = 1; off < NSEG; off <<= 1) {
        int val = (tid >= off) ? sh[tid - off] : 0;
        __syncthreads();
        sh[tid] += val;
        __syncthreads();
    }
    int excl = sh[tid] - my;
    g_offsets[tid] = excl;
    g_cursor[tid]  = excl;
}

// Phase 1d: scatter token indices into bucketed index list
__global__ void k_scatter(const int* __restrict__ ids) {
    int t = blockIdx.x * blockDim.x + threadIdx.x;
    if (t < NTOK) {
        int b = t >> 13;
        int v = ids[t];
        int pos = atomicAdd(&g_cursor[b * VV + v], 1);
        g_index[pos] = t;           // global row index into hidden_states
    }
}

// ---------------------------------------------------------------------------
// Phase 2: one CTA per (b, v) segment. Gather-sum its token rows (atomic-free,
// register accumulation, coalesced float4 loads), then project onto the 26
// classifier rows and write masked logits.
__global__ __launch_bounds__(192) void k_main(
    const float* __restrict__ h,      // [B*S, D]
    const float* __restrict__ Wm,     // [L, D]
    const float* __restrict__ bias,   // [L]
    float* __restrict__ out)          // [B, V, L]
{
    const int seg = blockIdx.x;
    const int v   = seg & (VV - 1);
    const int tid = threadIdx.x;      // 192 threads, one float4 (=4 floats) each

    const int cnt  = g_counts[seg];
    const int base = g_offsets[seg];

    float4 acc = make_float4(0.f, 0.f, 0.f, 0.f);

    const bool active = (v != 0) && (cnt > 0);
    if (active) {
        const float4* __restrict__ hp = (const float4*)h;   // row stride 192
        int i = 0;
        // Unroll-4 over tokens: 4 outstanding LDG.128 per thread for MLP
        for (; i + 4 <= cnt; i += 4) {
            int r0 = __ldg(&g_index[base + i]);
            int r1 = __ldg(&g_index[base + i + 1]);
            int r2 = __ldg(&g_index[base + i + 2]);
            int r3 = __ldg(&g_index[base + i + 3]);
            float4 a = __ldg(&hp[(long)r0 * (DD / 4) + tid]);
            float4 b = __ldg(&hp[(long)r1 * (DD / 4) + tid]);
            float4 c = __ldg(&hp[(long)r2 * (DD / 4) + tid]);
            float4 d = __ldg(&hp[(long)r3 * (DD / 4) + tid]);
            acc.x += (a.x + b.x) + (c.x + d.x);
            acc.y += (a.y + b.y) + (c.y + d.y);
            acc.z += (a.z + b.z) + (c.z + d.z);
            acc.w += (a.w + b.w) + (c.w + d.w);
        }
        for (; i < cnt; ++i) {
            int r = __ldg(&g_index[base + i]);
            float4 a = __ldg(&hp[(long)r * (DD / 4) + tid]);
            acc.x += a.x; acc.y += a.y; acc.z += a.z; acc.w += a.w;
        }
    }

    // Stage segment sum into shared memory for the projection
    __shared__ float ssum[DD];
    ((float4*)ssum)[tid] = acc;
    __syncthreads();

    // Epilogue: 6 warps, warp w handles labels l = w, w+6, ...
    const int warp = tid >> 5;
    const int lane = tid & 31;
    const float inv = 1.0f / (float)(cnt > 0 ? cnt : 1);

    for (int l = warp; l < LL; l += 6) {
        float s = 0.f;
        #pragma unroll
        for (int k = lane; k < DD; k += 32)
            s += ssum[k] * __ldg(&Wm[l * DD + k]);
        #pragma unroll
        for (int o = 16; o; o >>= 1)
            s += __shfl_xor_sync(0xffffffffu, s, o);
        if (lane == 0) {
            float r = active ? (s * inv + __ldg(&bias[l])) : 0.0f;
            out[seg * LL + l] = r;
        }
    }
}

// ---------------------------------------------------------------------------
extern "C" void kernel_launch(void* const* d_in, const int* in_sizes, int n_in,
                              void* d_out, int out_size) {
    // Map inputs by element count (all sizes distinct) for robustness.
    const float* h    = nullptr;   // 50331648
    const float* Wm   = nullptr;   // 19968
    const float* bias = nullptr;   // 26
    const int*   ids  = nullptr;   // 65536
    for (int i = 0; i < n_in; ++i) {
        switch (in_sizes[i]) {
            case BB * SS * DD: h    = (const float*)d_in[i]; break;
            case LL * DD:      Wm   = (const float*)d_in[i]; break;
            case LL:           bias = (const float*)d_in[i]; break;
            case BB * SS:      ids  = (const int*)d_in[i];   break;
        }
    }
    float* out = (float*)d_out;

    k_zero<<<1, NSEG>>>();
    k_hist<<<NTOK / 256, 256>>>(ids);
    k_scan<<<1, NSEG>>>();
    k_scatter<<<NTOK / 256, 256>>>(ids);
    k_main<<<NSEG, 192>>>(h, Wm, bias, out);
}

// round 3
// speedup vs baseline: 1.1468x; 1.1468x over previous
#include <cuda_runtime.h>

// Problem constants (fixed by the reference)
#define BB 8
#define SS 8192
#define DD 768
#define VV 64
#define LL 26
#define NSEG (BB * VV)   // 512

// One fused kernel: each CTA owns one (batch, symbol) segment.
//  Phase A: scan this batch's 8192 ids, append matching positions to a smem list.
//  Phase B: gather-sum the matching hidden rows (coalesced float4, unroll-8).
//  Phase C: mean + tiny 26-way linear head, masked write.
__global__ __launch_bounds__(192) void k_fused(
    const float* __restrict__ h,      // [B*S, D]
    const int*   __restrict__ ids,    // [B*S]
    const float* __restrict__ Wm,     // [L, D]
    const float* __restrict__ bias,   // [L]
    float* __restrict__ out)          // [B, V, L]
{
    const int seg = blockIdx.x;
    const int b   = seg >> 6;         // seg / V
    const int v   = seg & (VV - 1);
    const int tid = threadIdx.x;      // 192 threads = one float4 lane each (D/4)

    // ssum FIRST and explicitly 16B-aligned: it is accessed as float4.
    __shared__ __align__(16) float ssum[DD];
    __shared__ int   slist[SS];       // worst case: every token matches (32 KB)
    __shared__ int   scount;

    if (tid == 0) scount = 0;
    __syncthreads();

    // ---- Phase A: build index list for this segment (skip for symbol 0) ----
    if (v != 0) {
        const int* __restrict__ idb = ids + b * SS;
        #pragma unroll 4
        for (int s = tid; s < SS; s += 192) {
            if (__ldg(&idb[s]) == v) {
                int p = atomicAdd(&scount, 1);
                slist[p] = s;
            }
        }
    }
    __syncthreads();

    const int  cnt    = scount;
    const bool active = (v != 0) && (cnt > 0);

    // ---- Phase B: gather-sum rows ----
    float4 acc = make_float4(0.f, 0.f, 0.f, 0.f);
    if (active) {
        const float4* __restrict__ hb = (const float4*)h + (long)b * SS * (DD / 4);
        int i = 0;
        for (; i + 8 <= cnt; i += 8) {
            float4 t0 = __ldg(&hb[(long)slist[i + 0] * (DD / 4) + tid]);
            float4 t1 = __ldg(&hb[(long)slist[i + 1] * (DD / 4) + tid]);
            float4 t2 = __ldg(&hb[(long)slist[i + 2] * (DD / 4) + tid]);
            float4 t3 = __ldg(&hb[(long)slist[i + 3] * (DD / 4) + tid]);
            float4 t4 = __ldg(&hb[(long)slist[i + 4] * (DD / 4) + tid]);
            float4 t5 = __ldg(&hb[(long)slist[i + 5] * (DD / 4) + tid]);
            float4 t6 = __ldg(&hb[(long)slist[i + 6] * (DD / 4) + tid]);
            float4 t7 = __ldg(&hb[(long)slist[i + 7] * (DD / 4) + tid]);
            acc.x += ((t0.x + t1.x) + (t2.x + t3.x)) + ((t4.x + t5.x) + (t6.x + t7.x));
            acc.y += ((t0.y + t1.y) + (t2.y + t3.y)) + ((t4.y + t5.y) + (t6.y + t7.y));
            acc.z += ((t0.z + t1.z) + (t2.z + t3.z)) + ((t4.z + t5.z) + (t6.z + t7.z));
            acc.w += ((t0.w + t1.w) + (t2.w + t3.w)) + ((t4.w + t5.w) + (t6.w + t7.w));
        }
        for (; i < cnt; ++i) {
            float4 t = __ldg(&hb[(long)slist[i] * (DD / 4) + tid]);
            acc.x += t.x; acc.y += t.y; acc.z += t.z; acc.w += t.w;
        }
    }

    ((float4*)ssum)[tid] = acc;
    __syncthreads();

    // ---- Phase C: mean + linear head (6 warps over 26 labels) ----
    const int   warp = tid >> 5;
    const int   lane = tid & 31;
    const float inv  = 1.0f / (float)(cnt > 0 ? cnt : 1);

    for (int l = warp; l < LL; l += 6) {
        float s = 0.f;
        #pragma unroll
        for (int k = lane; k < DD; k += 32)
            s += ssum[k] * __ldg(&Wm[l * DD + k]);
        #pragma unroll
        for (int o = 16; o; o >>= 1)
            s += __shfl_xor_sync(0xffffffffu, s, o);
        if (lane == 0)
            out[seg * LL + l] = active ? (s * inv + __ldg(&bias[l])) : 0.0f;
    }
}

// ---------------------------------------------------------------------------
extern "C" void kernel_launch(void* const* d_in, const int* in_sizes, int n_in,
                              void* d_out, int out_size) {
    const float* h    = nullptr;   // 50331648
    const float* Wm   = nullptr;   // 19968
    const float* bias = nullptr;   // 26
    const int*   ids  = nullptr;   // 65536
    for (int i = 0; i < n_in; ++i) {
        switch (in_sizes[i]) {
            case BB * SS * DD: h    = (const float*)d_in[i]; break;
            case LL * DD:      Wm   = (const float*)d_in[i]; break;
            case LL:           bias = (const float*)d_in[i]; break;
            case BB * SS:      ids  = (const int*)d_in[i];   break;
        }
    }
    float* out = (float*)d_out;

    k_fused<<<NSEG, 192>>>(h, ids, Wm, bias, out);
}

// round 4
// speedup vs baseline: 1.2092x; 1.0544x over previous
#include <cuda_runtime.h>

// Problem constants (fixed by the reference)
#define BB 8
#define SS 8192
#define DD 768
#define VV 64
#define LL 26
#define NSEG   (BB * VV)        // 512
#define SPLIT  4
#define SCHUNK (SS / SPLIT)     // 2048 tokens per split
#define NPART  (NSEG * SPLIT)   // 2048 CTAs in main kernel

// Global scratch: per-(segment, split) partial sums and counts.
__device__ __align__(16) float g_part[NPART * DD];  // ~6.3 MB
__device__ int g_pcnt[NPART];

// ---------------------------------------------------------------------------
// Kernel 1: one CTA per (segment, split-chunk).
//  Phase A: scan this chunk's 2048 ids, build smem index list.
//  Phase B: gather-sum matching rows (coalesced float4, unroll-8), write
//           partial sum straight to global scratch (one float4 per thread).
__global__ __launch_bounds__(192) void k_gather(
    const float* __restrict__ h,      // [B*S, D]
    const int*   __restrict__ ids)    // [B*S]
{
    const int part = blockIdx.x;          // 0 .. NPART-1
    const int seg  = part >> 2;           // / SPLIT
    const int sp   = part & (SPLIT - 1);
    const int b    = seg >> 6;
    const int v    = seg & (VV - 1);
    const int tid  = threadIdx.x;         // 192 threads = D/4 float4 lanes

    __shared__ int slist[SCHUNK];         // 8 KB worst case
    __shared__ int scount;

    if (tid == 0) scount = 0;
    __syncthreads();

    if (v == 0) {                         // symbol 0 masked: no work, no write
        if (tid == 0) g_pcnt[part] = 0;
        return;
    }

    // ---- Phase A: index list for this chunk ----
    const int s0 = sp * SCHUNK;
    const int* __restrict__ idb = ids + b * SS + s0;
    #pragma unroll 4
    for (int s = tid; s < SCHUNK; s += 192) {
        if (__ldg(&idb[s]) == v) {
            int p = atomicAdd(&scount, 1);
            slist[p] = s0 + s;
        }
    }
    __syncthreads();
    const int cnt = scount;

    // ---- Phase B: gather-sum rows ----
    float4 acc = make_float4(0.f, 0.f, 0.f, 0.f);
    const float4* __restrict__ hb = (const float4*)h + (long)b * SS * (DD / 4);
    int i = 0;
    for (; i + 8 <= cnt; i += 8) {
        float4 t0 = __ldg(&hb[(long)slist[i + 0] * (DD / 4) + tid]);
        float4 t1 = __ldg(&hb[(long)slist[i + 1] * (DD / 4) + tid]);
        float4 t2 = __ldg(&hb[(long)slist[i + 2] * (DD / 4) + tid]);
        float4 t3 = __ldg(&hb[(long)slist[i + 3] * (DD / 4) + tid]);
        float4 t4 = __ldg(&hb[(long)slist[i + 4] * (DD / 4) + tid]);
        float4 t5 = __ldg(&hb[(long)slist[i + 5] * (DD / 4) + tid]);
        float4 t6 = __ldg(&hb[(long)slist[i + 6] * (DD / 4) + tid]);
        float4 t7 = __ldg(&hb[(long)slist[i + 7] * (DD / 4) + tid]);
        acc.x += ((t0.x + t1.x) + (t2.x + t3.x)) + ((t4.x + t5.x) + (t6.x + t7.x));
        acc.y += ((t0.y + t1.y) + (t2.y + t3.y)) + ((t4.y + t5.y) + (t6.y + t7.y));
        acc.z += ((t0.z + t1.z) + (t2.z + t3.z)) + ((t4.z + t5.z) + (t6.z + t7.z));
        acc.w += ((t0.w + t1.w) + (t2.w + t3.w)) + ((t4.w + t5.w) + (t6.w + t7.w));
    }
    for (; i < cnt; ++i) {
        float4 t = __ldg(&hb[(long)slist[i] * (DD / 4) + tid]);
        acc.x += t.x; acc.y += t.y; acc.z += t.z; acc.w += t.w;
    }

    ((float4*)g_part)[(long)part * (DD / 4) + tid] = acc;
    if (tid == 0) g_pcnt[part] = cnt;
}

// ---------------------------------------------------------------------------
// Kernel 2: one CTA per segment. Sum the SPLIT partials, mean + linear head.
__global__ __launch_bounds__(192) void k_head(
    const float* __restrict__ Wm,     // [L, D]
    const float* __restrict__ bias,   // [L]
    float* __restrict__ out)          // [B, V, L]
{
    const int seg = blockIdx.x;
    const int v   = seg & (VV - 1);
    const int tid = threadIdx.x;

    __shared__ __align__(16) float ssum[DD];

    int cnt = 0;
    float4 acc = make_float4(0.f, 0.f, 0.f, 0.f);

    if (v != 0) {
        #pragma unroll
        for (int sp = 0; sp < SPLIT; ++sp) {
            const int part = seg * SPLIT + sp;
            cnt += g_pcnt[part];
            float4 t = ((const float4*)g_part)[(long)part * (DD / 4) + tid];
            acc.x += t.x; acc.y += t.y; acc.z += t.z; acc.w += t.w;
        }
    }
    ((float4*)ssum)[tid] = acc;
    __syncthreads();

    const bool  active = (v != 0) && (cnt > 0);
    const int   warp = tid >> 5;
    const int   lane = tid & 31;
    const float inv  = 1.0f / (float)(cnt > 0 ? cnt : 1);

    for (int l = warp; l < LL; l += 6) {
        float s = 0.f;
        #pragma unroll
        for (int k = lane; k < DD; k += 32)
            s += ssum[k] * __ldg(&Wm[l * DD + k]);
        #pragma unroll
        for (int o = 16; o; o >>= 1)
            s += __shfl_xor_sync(0xffffffffu, s, o);
        if (lane == 0)
            out[seg * LL + l] = active ? (s * inv + __ldg(&bias[l])) : 0.0f;
    }
}

// ---------------------------------------------------------------------------
extern "C" void kernel_launch(void* const* d_in, const int* in_sizes, int n_in,
                              void* d_out, int out_size) {
    const float* h    = nullptr;   // 50331648
    const float* Wm   = nullptr;   // 19968
    const float* bias = nullptr;   // 26
    const int*   ids  = nullptr;   // 65536
    for (int i = 0; i < n_in; ++i) {
        switch (in_sizes[i]) {
            case BB * SS * DD: h    = (const float*)d_in[i]; break;
            case LL * DD:      Wm   = (const float*)d_in[i]; break;
            case LL:           bias = (const float*)d_in[i]; break;
            case BB * SS:      ids  = (const int*)d_in[i];   break;
        }
    }
    float* out = (float*)d_out;

    k_gather<<<NPART, 192>>>(h, ids);
    k_head<<<NSEG, 192>>>(Wm, bias, out);
}